// round 5
// baseline (speedup 1.0000x reference)
#include <cuda_runtime.h>
#include <stdint.h>
#include <math.h>

#define TOPK 1000
#define DETS 300
#define NB    4608          // bins over (0.05, 1.0] via fb>>13 - BASE
#define CH    18            // NB / 256
#define BASE  125542        // 0x3D4CCCCD >> 13  (0.05f)
#define CAND_CAP 32768
#define SELCAP   6144
#define NCLS  80
#define CLSCAP 1024
#define WCAP_S 6144

#define HIST_GRID 592
#define SEL_GRID  16

__device__ unsigned int       g_hist1[NB];
__device__ unsigned int       g_sel[8];          // [0]=B1 [2]=cand cnt [6]=hist ticket [7]=sel ticket
__device__ unsigned long long g_cand[CAND_CAP];
__device__ int                g_topIdx[TOPK];
__device__ float              g_topVal[TOPK];
__device__ float              g_bk[TOPK*5];      // original boxes (output)
__device__ float              g_nms[TOPK*5];     // offset boxes (NMS domain)
__device__ float              g_corn[TOPK*8];
__device__ float              g_aabb[TOPK*4];    // minx,maxx,miny,maxy
__device__ float              g_area[TOPK];
__device__ int                g_clsCnt[NCLS];
__device__ int                g_clsIdx[NCLS*CLSCAP];
__device__ int                g_lab[TOPK];

__device__ __forceinline__ float neginf() { return __int_as_float(0xff800000); }

__device__ __forceinline__ int bin_of(unsigned fb) {
    int b = (int)(fb >> 13) - BASE;
    if (b < 0) b = 0;
    if (b > NB - 1) b = NB - 1;
    return b;
}

// ---------------------------------------------------------------- reset
__global__ void k_reset() {
    int i  = blockIdx.x * blockDim.x + threadIdx.x;
    int st = gridDim.x * blockDim.x;
    for (int k = i; k < NB;   k += st) g_hist1[k] = 0;
    for (int k = i; k < 8;    k += st) g_sel[k]   = 0;
    for (int k = i; k < NCLS; k += st) g_clsCnt[k] = 0;
    for (int k = i; k < TOPK; k += st) {
        g_topIdx[k] = -1;
        g_topVal[k] = neginf();
    }
}

// ---------------------------------------------------------------- pass 1: histogram + fused findb1 (last block)
__global__ void k_hist(const float4* __restrict__ sc4, int n4) {
    __shared__ unsigned int h[NB];
    __shared__ unsigned csum[256];
    __shared__ int isLast;
    int tid = threadIdx.x;
    for (int k = tid; k < NB; k += blockDim.x) h[k] = 0;
    __syncthreads();
    int i0 = blockIdx.x * blockDim.x + tid;
    int S  = gridDim.x * blockDim.x;
    for (int p = i0; p < n4; p += 4 * S) {
        int p1 = p + S, p2 = p + 2*S, p3 = p + 3*S;
        float4 v0 = sc4[p];
        float4 v1 = (p1 < n4) ? sc4[p1] : make_float4(0,0,0,0);
        float4 v2 = (p2 < n4) ? sc4[p2] : make_float4(0,0,0,0);
        float4 v3 = (p3 < n4) ? sc4[p3] : make_float4(0,0,0,0);
        float vs[16] = { v0.x,v0.y,v0.z,v0.w, v1.x,v1.y,v1.z,v1.w,
                         v2.x,v2.y,v2.z,v2.w, v3.x,v3.y,v3.z,v3.w };
#pragma unroll
        for (int l = 0; l < 16; l++) {
            float s = vs[l];
            if (s > 0.05f) atomicAdd(&h[bin_of(__float_as_uint(s))], 1u);
        }
    }
    __syncthreads();
    for (int k = tid; k < NB; k += blockDim.x) {
        unsigned v = h[k];
        if (v) atomicAdd(&g_hist1[k], v);
    }
    __threadfence();
    if (tid == 0) {
        unsigned t = atomicAdd(&g_sel[6], 1u);
        isLast = (t == gridDim.x - 1);
    }
    __syncthreads();
    if (!isLast) return;
    __threadfence();
    // ---- fused findb1 ----
    for (int k = tid; k < NB; k += blockDim.x) h[k] = g_hist1[k];
    __syncthreads();
    unsigned s = 0;
    for (int b = tid * CH; b < tid * CH + CH; b++) s += h[b];
    csum[tid] = s;
    __syncthreads();
    if (tid == 0) {
        unsigned cum = 0; int B1 = -1;
        for (int c = 255; c >= 0; c--) {
            if (cum + csum[c] >= TOPK) {
                for (int b = c * CH + CH - 1; b >= c * CH; b--) {
                    if (cum + h[b] >= TOPK) { B1 = b; break; }
                    cum += h[b];
                }
                break;
            }
            cum += csum[c];
        }
        if (B1 < 0) B1 = 0;
        g_sel[0] = (unsigned)B1;
    }
}

// ---------------------------------------------------------------- pass 2: compact (bin >= B1)
__global__ void k_compact(const float4* __restrict__ sc4, int n4) {
    unsigned B1 = g_sel[0];
    int i0 = blockIdx.x * blockDim.x + threadIdx.x;
    int S  = gridDim.x * blockDim.x;
    for (int p = i0; p < n4; p += 2 * S) {
        int p1 = p + S;
        float4 v0 = sc4[p];
        float4 v1 = (p1 < n4) ? sc4[p1] : make_float4(0,0,0,0);
        float vs[8] = { v0.x,v0.y,v0.z,v0.w, v1.x,v1.y,v1.z,v1.w };
        int   pb[2] = { p, p1 };
#pragma unroll
        for (int l = 0; l < 8; l++) {
            float s = vs[l];
            if (s > 0.05f) {
                unsigned fb = __float_as_uint(s);
                if (bin_of(fb) >= (int)B1) {
                    unsigned pos = atomicAdd(&g_sel[2], 1u);
                    if (pos < CAND_CAP) {
                        unsigned idx = (unsigned)(pb[l >> 2] * 4 + (l & 3));
                        g_cand[pos] = ((unsigned long long)fb << 32) |
                                      (unsigned long long)(0xFFFFFFFFu - idx);
                    }
                }
            }
        }
    }
}

// ---------------------------------------------------------------- select + fused prep (last block)
__global__ void k_selprep(const float* __restrict__ boxes, const int* __restrict__ labels) {
    __shared__ unsigned long long sk[SELCAP];
    __shared__ int isLast;
    unsigned C = g_sel[2];
    if (C > CAND_CAP) C = CAND_CAP;
    int tid = threadIdx.x;
    int gid = blockIdx.x * blockDim.x + tid;
    int st  = gridDim.x * blockDim.x;
    if (C <= SELCAP) {
        for (unsigned k = (unsigned)tid; k < C; k += blockDim.x) sk[k] = g_cand[k];
        __syncthreads();
        for (unsigned c = (unsigned)gid; c < C; c += (unsigned)st) {
            unsigned long long key = sk[c];
            int rank = 0;
            for (unsigned k = 0; k < C; k++) rank += (sk[k] > key) ? 1 : 0;
            if (rank < TOPK) {
                g_topIdx[rank] = (int)(0xFFFFFFFFu - (unsigned)(key & 0xFFFFFFFFull));
                g_topVal[rank] = __uint_as_float((unsigned)(key >> 32));
            }
        }
    } else {
        for (unsigned c = (unsigned)gid; c < C; c += (unsigned)st) {
            unsigned long long key = g_cand[c];
            int rank = 0;
            for (unsigned k = 0; k < C; k++) rank += (g_cand[k] > key) ? 1 : 0;
            if (rank < TOPK) {
                g_topIdx[rank] = (int)(0xFFFFFFFFu - (unsigned)(key & 0xFFFFFFFFull));
                g_topVal[rank] = __uint_as_float((unsigned)(key >> 32));
            }
        }
    }
    __threadfence();
    __syncthreads();
    if (tid == 0) {
        unsigned t = atomicAdd(&g_sel[7], 1u);
        isLast = (t == gridDim.x - 1);
    }
    __syncthreads();
    if (!isLast) return;
    __threadfence();
    // ---- fused prep: gather + offset + corners + AABB + class lists ----
    for (int i = tid; i < TOPK; i += blockDim.x) {
        int idx = g_topIdx[i];
        if (idx < 0) { g_lab[i] = -2 - i; g_area[i] = 0.0f; continue; }
        float cx = boxes[idx*5+0], cy = boxes[idx*5+1];
        float w  = boxes[idx*5+2], h  = boxes[idx*5+3];
        float a  = boxes[idx*5+4];
        g_bk[i*5+0]=cx; g_bk[i*5+1]=cy; g_bk[i*5+2]=w; g_bk[i*5+3]=h; g_bk[i*5+4]=a;
        int lab = labels[idx];
        g_lab[i] = lab;
        float off = __fmul_rn((float)lab, 10000.0f);
        float cxo = __fadd_rn(cx, off);
        float cyo = __fadd_rn(cy, off);
        g_nms[i*5+0]=cxo; g_nms[i*5+1]=cyo; g_nms[i*5+2]=w; g_nms[i*5+3]=h; g_nms[i*5+4]=a;
        g_area[i] = __fmul_rn(w, h);

        float c = cosf(a), s = sinf(a);
        float dx = __fmul_rn(w, 0.5f), dy = __fmul_rn(h, 0.5f);
        float ox[4] = { dx, -dx, -dx,  dx };
        float oy[4] = { dy,  dy, -dy, -dy };
        float mnx =  3.4e38f, mxx = -3.4e38f, mny = 3.4e38f, mxy = -3.4e38f;
#pragma unroll
        for (int j = 0; j < 4; j++) {
            float x = __fsub_rn(__fadd_rn(cxo, __fmul_rn(ox[j], c)), __fmul_rn(oy[j], s));
            float y = __fadd_rn(__fadd_rn(cyo, __fmul_rn(ox[j], s)), __fmul_rn(oy[j], c));
            g_corn[i*8 + 2*j]     = x;
            g_corn[i*8 + 2*j + 1] = y;
            mnx = fminf(mnx, x); mxx = fmaxf(mxx, x);
            mny = fminf(mny, y); mxy = fmaxf(mxy, y);
        }
        g_aabb[i*4+0]=mnx; g_aabb[i*4+1]=mxx; g_aabb[i*4+2]=mny; g_aabb[i*4+3]=mxy;
        if (lab >= 0 && lab < NCLS) {
            int pos = atomicAdd(&g_clsCnt[lab], 1);
            if (pos < CLSCAP) g_clsIdx[lab*CLSCAP + pos] = i;
        }
    }
}

// ---------------------------------------------------------------- exact replica of _pair_inter_area (fp32, no FMA, seq order)
__device__ float pair_inter_area(const float* A, const float* cA,
                                 const float* B, const float* cB) {
    const float eps = 1e-6f;
    const float ONEPE = 1.000001f;
    float px[24], py[24];
    bool  vl[24];
    float ax[4], ay[4], bx[4], by[4];
#pragma unroll
    for (int k = 0; k < 4; k++) {
        ax[k]=cA[2*k]; ay[k]=cA[2*k+1]; bx[k]=cB[2*k]; by[k]=cB[2*k+1];
        px[k]=ax[k]; py[k]=ay[k]; px[4+k]=bx[k]; py[4+k]=by[k];
    }
    {   // vA = in_box(cornA, boxB)
        float c = cosf(B[4]), s = sinf(B[4]);
        float lw = __fadd_rn(__fmul_rn(B[2], 0.5f), eps);
        float lh = __fadd_rn(__fmul_rn(B[3], 0.5f), eps);
#pragma unroll
        for (int k = 0; k < 4; k++) {
            float rx = __fsub_rn(ax[k], B[0]), ry = __fsub_rn(ay[k], B[1]);
            float xr = __fadd_rn(__fmul_rn(rx, c), __fmul_rn(ry, s));
            float yr = __fadd_rn(__fmul_rn(-rx, s), __fmul_rn(ry, c));
            vl[k] = (fabsf(xr) <= lw) && (fabsf(yr) <= lh);
        }
    }
    {   // vB = in_box(cornB, boxA)
        float c = cosf(A[4]), s = sinf(A[4]);
        float lw = __fadd_rn(__fmul_rn(A[2], 0.5f), eps);
        float lh = __fadd_rn(__fmul_rn(A[3], 0.5f), eps);
#pragma unroll
        for (int k = 0; k < 4; k++) {
            float rx = __fsub_rn(bx[k], A[0]), ry = __fsub_rn(by[k], A[1]);
            float xr = __fadd_rn(__fmul_rn(rx, c), __fmul_rn(ry, s));
            float yr = __fadd_rn(__fmul_rn(-rx, s), __fmul_rn(ry, c));
            vl[4+k] = (fabsf(xr) <= lw) && (fabsf(yr) <= lh);
        }
    }
    float dAx[4],dAy[4],dBx[4],dBy[4];
#pragma unroll
    for (int k = 0; k < 4; k++) {
        dAx[k]=__fsub_rn(ax[(k+1)&3],ax[k]); dAy[k]=__fsub_rn(ay[(k+1)&3],ay[k]);
        dBx[k]=__fsub_rn(bx[(k+1)&3],bx[k]); dBy[k]=__fsub_rn(by[(k+1)&3],by[k]);
    }
#pragma unroll
    for (int i = 0; i < 4; i++) {
#pragma unroll
        for (int j = 0; j < 4; j++) {
            float rx  = __fsub_rn(bx[j], ax[i]), ry = __fsub_rn(by[j], ay[i]);
            float den = __fsub_rn(__fmul_rn(dAx[i], dBy[j]), __fmul_rn(dAy[i], dBx[j]));
            float ad  = fabsf(den);
            float dens = (ad < 1e-9f) ? 1.0f : den;
            float t = __fsub_rn(__fmul_rn(rx, dBy[j]), __fmul_rn(ry, dBx[j])) / dens;
            float u = __fsub_rn(__fmul_rn(rx, dAy[i]), __fmul_rn(ry, dAx[i])) / dens;
            bool v  = (ad > 1e-9f) && (t >= -eps) && (t <= ONEPE) && (u >= -eps) && (u <= ONEPE);
            int o = 8 + i*4 + j;
            px[o] = __fadd_rn(ax[i], __fmul_rn(t, dAx[i]));
            py[o] = __fadd_rn(ay[i], __fmul_rn(t, dAy[i]));
            vl[o] = v;
        }
    }
    int cnt = 0;
#pragma unroll
    for (int k = 0; k < 24; k++) cnt += vl[k] ? 1 : 0;
    float sx = 0.0f, sy = 0.0f;
#pragma unroll
    for (int k = 0; k < 24; k++) {
        float f = vl[k] ? 1.0f : 0.0f;
        sx = __fadd_rn(sx, __fmul_rn(px[k], f));
        sy = __fadd_rn(sy, __fmul_rn(py[k], f));
    }
    int cm = cnt > 1 ? cnt : 1;
    float cenx = sx / (float)cm, ceny = sy / (float)cm;
    int am = 0;
#pragma unroll
    for (int k = 23; k >= 0; k--) if (vl[k]) am = k;
    float anx = px[am], anyy = py[am];
    float qx[24], qy[24], ang[24];
#pragma unroll
    for (int k = 0; k < 24; k++) {
        qx[k] = vl[k] ? px[k] : anx;
        qy[k] = vl[k] ? py[k] : anyy;
        ang[k] = atan2f(__fsub_rn(qy[k], ceny), __fsub_rn(qx[k], cenx));
    }
    int ord[24];
    for (int k = 0; k < 24; k++) ord[k] = k;
    for (int k = 1; k < 24; k++) {
        int o = ord[k]; float a = ang[o]; int m = k - 1;
        while (m >= 0 && ang[ord[m]] > a) { ord[m+1] = ord[m]; m--; }
        ord[m+1] = o;
    }
    float ssum = 0.0f;
    for (int k = 0; k < 24; k++) {
        int k0 = ord[k], k1 = ord[(k + 1) % 24];
        float term = __fsub_rn(__fmul_rn(qx[k0], qy[k1]), __fmul_rn(qx[k1], qy[k0]));
        ssum = __fadd_rn(ssum, term);
    }
    float area = __fmul_rn(0.5f, fabsf(ssum));
    return (cnt >= 3) ? area : 0.0f;
}

// ---------------------------------------------------------------- fused: pair sieve + clips + serial NMS + output (1 block, 256 thr)
__global__ void __launch_bounds__(256, 1) k_final(float* __restrict__ out) {
    extern __shared__ unsigned s_mem[];
    unsigned* s_sup = s_mem;                 // TOPK*32 = 32000 words
    unsigned* s_wl  = s_mem + TOPK*32;       // WCAP_S words
    __shared__ unsigned keepW[32];
    __shared__ unsigned raW[32];
    __shared__ int lst[DETS];
    __shared__ int kcnt;
    __shared__ int wcnt;
    int tid = threadIdx.x;
    int nt  = blockDim.x;

    for (int k = tid; k < TOPK*32; k += nt) s_sup[k] = 0u;
    if (tid < 32) { keepW[tid] = 0u; raW[tid] = 0u; }
    if (tid == 0) wcnt = 0;
    __syncthreads();
    for (int i = tid; i < TOPK; i += nt) {
        if (g_topVal[i] > neginf()) atomicOr(&keepW[i >> 5], 1u << (i & 31));
    }

    // ---- pair sieve, per class ----
    for (int c = 0; c < NCLS; c++) {
        int n = g_clsCnt[c];
        if (n > CLSCAP) n = CLSCAP;
        if (n < 2) continue;
        const int* cl = &g_clsIdx[c*CLSCAP];
        for (int t = tid; t < n*n; t += nt) {
            int i_ = t / n, j_ = t - i_ * n;
            if (i_ >= j_) continue;
            int a = cl[i_], b = cl[j_];
            if (a > b) { int tmp = a; a = b; b = tmp; }
            const float M = 1.0f;
            if (g_aabb[a*4+0] > g_aabb[b*4+1] + M || g_aabb[b*4+0] > g_aabb[a*4+1] + M ||
                g_aabb[a*4+2] > g_aabb[b*4+3] + M || g_aabb[b*4+2] > g_aabb[a*4+3] + M) continue;
            int pos = atomicAdd(&wcnt, 1);
            if (pos < WCAP_S) s_wl[pos] = ((unsigned)a << 16) | (unsigned)b;
        }
    }
    __syncthreads();

    // ---- heavy clips ----
    int W = wcnt; if (W > WCAP_S) W = WCAP_S;
    for (int w = tid; w < W; w += nt) {
        unsigned e = s_wl[w];
        int i = (int)(e >> 16), j = (int)(e & 0xFFFFu);
        float inter = pair_inter_area(&g_nms[i*5], &g_corn[i*8], &g_nms[j*5], &g_corn[j*8]);
        float S   = __fadd_rn(__fsub_rn(__fadd_rn(g_area[i], g_area[j]), inter), 1e-6f);
        float iou = inter / S;
        if (iou > 0.5f) {
            atomicOr(&s_sup[i*32 + (j >> 5)], 1u << (j & 31));
            atomicOr(&raW[i >> 5], 1u << (i & 31));
        }
    }
    __syncthreads();

    // ---- serial NMS over rowAny rows only (warp 0) ----
    if (tid < 32) {
        for (int w = 0; w < 32; w++) {
            unsigned rbits = raW[w];
            while (rbits) {
                int b = __ffs(rbits) - 1;
                rbits &= rbits - 1;
                int i = w * 32 + b;
                if (keepW[w] & (1u << b)) {
                    keepW[tid] &= ~s_sup[i * 32 + tid];
                }
                __syncwarp();
            }
        }
    }
    __syncthreads();

    if (tid == 0) {
        int p = 0;
        for (int w = 0; w < 32 && p < DETS; w++) {
            unsigned m = keepW[w];
            while (m && p < DETS) {
                int b = __ffs(m) - 1;
                m &= m - 1;
                lst[p++] = w * 32 + b;
            }
        }
        kcnt = p;
    }
    __syncthreads();

    for (int r = tid; r < DETS; r += nt) {
        if (r < kcnt) {
            int i = lst[r];
#pragma unroll
            for (int k = 0; k < 5; k++) out[r*5+k] = g_bk[i*5+k];
            out[DETS*5 + r] = (float)g_lab[i];
            out[DETS*6 + r] = g_topVal[i];
        } else {
#pragma unroll
            for (int k = 0; k < 5; k++) out[r*5+k] = 0.0f;
            out[DETS*5 + r] = -1.0f;
            out[DETS*6 + r] = 0.0f;
        }
    }
}

// ---------------------------------------------------------------- launcher
extern "C" void kernel_launch(void* const* d_in, const int* in_sizes, int n_in,
                              void* d_out, int out_size) {
    const float* boxes  = (const float*)d_in[0];
    const float* scores = (const float*)d_in[1];
    const int*   labels = (const int*)d_in[2];
    int n = in_sizes[1];
    int n4 = n / 4;

    static const int FSMEM = (TOPK*32 + WCAP_S) * (int)sizeof(unsigned);
    cudaFuncSetAttribute(k_final, cudaFuncAttributeMaxDynamicSharedMemorySize, FSMEM);

    k_reset  <<<64, 256>>>();
    k_hist   <<<HIST_GRID, 256>>>((const float4*)scores, n4);
    k_compact<<<1184, 256>>>((const float4*)scores, n4);
    k_selprep<<<SEL_GRID, 256>>>(boxes, labels);
    k_final  <<<1, 256, FSMEM>>>((float*)d_out);
}